// round 1
// baseline (speedup 1.0000x reference)
#include <cuda_runtime.h>
#include <math.h>

// Problem constants
static constexpr int Bn  = 2048;   // batch
static constexpr int An  = 256;    // action space
static constexpr int NE  = 100000; // entities
static constexpr int NR  = 500;    // relations
static constexpr int ED  = 200;
static constexpr int RD  = 200;
static constexpr int HD  = 400;
static constexpr int AD  = 400;    // ED+RD
static constexpr int K1  = ED + HD + RD; // 800

// Scratch layout (floats)
static constexpr size_t OFF_X    = 0;                          // [Bn, 800]
static constexpr size_t OFF_H1   = OFF_X  + (size_t)Bn*K1;     // [Bn, 400]
static constexpr size_t OFF_X2   = OFF_H1 + (size_t)Bn*AD;     // [Bn, 400]
static constexpr size_t OFF_RS   = OFF_X2 + (size_t)Bn*AD;     // [Bn, 500]
static constexpr size_t OFF_RELT = OFF_RS + (size_t)Bn*NR;     // [200, 500]
static constexpr size_t SCRATCH_FLOATS = OFF_RELT + (size_t)RD*NR;

__device__ float g_scratch[SCRATCH_FLOATS];

// ---------------------------------------------------------------------------
// Build X = cat([entity_emb[e], H, relation_emb[q]])  -> [Bn, 800]
// ---------------------------------------------------------------------------
__global__ void build_x_kernel(const int* __restrict__ e, const int* __restrict__ q,
                               const float* __restrict__ H,
                               const float* __restrict__ ent,
                               const float* __restrict__ rel,
                               float* __restrict__ X)
{
    int b = blockIdx.x;
    float4* dst = reinterpret_cast<float4*>(X + (size_t)b * K1);
    const float4* es = reinterpret_cast<const float4*>(ent + (size_t)e[b] * ED);
    const float4* hs = reinterpret_cast<const float4*>(H   + (size_t)b * HD);
    const float4* qs = reinterpret_cast<const float4*>(rel + (size_t)q[b] * RD);
    for (int i = threadIdx.x; i < K1 / 4; i += blockDim.x) {
        float4 v;
        if (i < ED / 4)              v = es[i];
        else if (i < (ED + HD) / 4)  v = hs[i - ED / 4];
        else                         v = qs[i - (ED + HD) / 4];
        dst[i] = v;
    }
}

// ---------------------------------------------------------------------------
// Transpose relation_emb [NR, RD] -> relT [RD, NR]
// ---------------------------------------------------------------------------
__global__ void transpose_rel_kernel(const float* __restrict__ rel, float* __restrict__ relT)
{
    int t = blockIdx.x * blockDim.x + threadIdx.x;
    if (t < NR * RD) {
        int n = t / RD, k = t % RD;
        relT[k * NR + n] = rel[t];
    }
}

// ---------------------------------------------------------------------------
// Generic fp32 GEMM: C[M,N] = op(A[M,K] @ B[K,N] + bias)
// mode 0: +bias, relu ; mode 1: +bias ; mode 2: plain
// 64x64 tile, BK=16, 256 threads, 4x4 micro-tile
// ---------------------------------------------------------------------------
__global__ __launch_bounds__(256)
void gemm64_kernel(const float* __restrict__ Ap, const float* __restrict__ Bp,
                   const float* __restrict__ bias, float* __restrict__ Cp,
                   int M, int N, int K, int lda, int ldb, int ldc, int mode)
{
    __shared__ float As[16][64];
    __shared__ float Bs[16][64];

    const int tid = threadIdx.x;
    const int tx = tid & 15, ty = tid >> 4;
    const int bm = blockIdx.y * 64, bn = blockIdx.x * 64;

    const int aRow = tid >> 2, aCol = (tid & 3) * 4;   // A tile: 64 rows x 16 cols
    const int bRow = tid >> 4, bCol = (tid & 15) * 4;  // B tile: 16 rows x 64 cols

    float acc[4][4];
#pragma unroll
    for (int i = 0; i < 4; i++)
#pragma unroll
        for (int j = 0; j < 4; j++) acc[i][j] = 0.f;

    for (int k0 = 0; k0 < K; k0 += 16) {
        float4 av = make_float4(0.f, 0.f, 0.f, 0.f);
        int am = bm + aRow, ak = k0 + aCol;
        if (am < M && ak < K)
            av = *reinterpret_cast<const float4*>(Ap + (size_t)am * lda + ak);
        As[aCol + 0][aRow] = av.x;
        As[aCol + 1][aRow] = av.y;
        As[aCol + 2][aRow] = av.z;
        As[aCol + 3][aRow] = av.w;

        float4 bv = make_float4(0.f, 0.f, 0.f, 0.f);
        int bk = k0 + bRow, bnn = bn + bCol;
        if (bk < K && bnn < N)
            bv = *reinterpret_cast<const float4*>(Bp + (size_t)bk * ldb + bnn);
        *reinterpret_cast<float4*>(&Bs[bRow][bCol]) = bv;

        __syncthreads();

#pragma unroll
        for (int kk = 0; kk < 16; kk++) {
            float4 a = *reinterpret_cast<const float4*>(&As[kk][ty * 4]);
            float4 b = *reinterpret_cast<const float4*>(&Bs[kk][tx * 4]);
            float ar[4] = {a.x, a.y, a.z, a.w};
            float br[4] = {b.x, b.y, b.z, b.w};
#pragma unroll
            for (int i = 0; i < 4; i++)
#pragma unroll
                for (int j = 0; j < 4; j++)
                    acc[i][j] += ar[i] * br[j];
        }
        __syncthreads();
    }

#pragma unroll
    for (int i = 0; i < 4; i++) {
        int m = bm + ty * 4 + i;
        if (m >= M) continue;
#pragma unroll
        for (int j = 0; j < 4; j++) {
            int n = bn + tx * 4 + j;
            if (n >= N) continue;
            float v = acc[i][j];
            if (mode < 2) v += bias[n];
            if (mode == 0) v = fmaxf(v, 0.f);
            Cp[(size_t)m * ldc + n] = v;
        }
    }
}

// ---------------------------------------------------------------------------
// Scores + softmax + entropy. One block per batch row, 256 threads (one/action).
// score[b,a] = RS[b, r_space] + dot(ent_emb[e_space], X2[b,200:400]) - (1-mask)*1e9
// ---------------------------------------------------------------------------
__global__ __launch_bounds__(256)
void score_softmax_kernel(const int* __restrict__ r_space,
                          const int* __restrict__ e_space,
                          const int* __restrict__ mask,
                          const float* __restrict__ ent,
                          const float* __restrict__ X2,
                          const float* __restrict__ RS,
                          float* __restrict__ out_dist,
                          float* __restrict__ out_entropy)
{
    __shared__ float x2s[AD];
    __shared__ float red[8];
    __shared__ float bcast;

    const int b = blockIdx.x;
    const int t = threadIdx.x;
    const int lane = t & 31, wid = t >> 5;

    for (int i = t; i < AD; i += 256) x2s[i] = X2[(size_t)b * AD + i];
    __syncthreads();

    const int idx = b * An + t;
    const int r  = r_space[idx];
    const int ei = e_space[idx];
    const float m = (float)mask[idx];

    float s = RS[(size_t)b * NR + r];

    const float4* erow = reinterpret_cast<const float4*>(ent + (size_t)ei * ED);
    const float4* xv   = reinterpret_cast<const float4*>(x2s + RD);
    float acc = 0.f;
#pragma unroll
    for (int i = 0; i < ED / 4; i++) {
        float4 v = erow[i];
        float4 x = xv[i];
        acc += v.x * x.x;
        acc += v.y * x.y;
        acc += v.z * x.z;
        acc += v.w * x.w;
    }
    s += acc;
    s -= (1.0f - m) * 1e9f;

    // block max
    float mx = s;
#pragma unroll
    for (int o = 16; o; o >>= 1) mx = fmaxf(mx, __shfl_xor_sync(0xffffffffu, mx, o));
    if (lane == 0) red[wid] = mx;
    __syncthreads();
    if (t == 0) {
        float v = red[0];
#pragma unroll
        for (int i = 1; i < 8; i++) v = fmaxf(v, red[i]);
        bcast = v;
    }
    __syncthreads();
    mx = bcast;

    // block sum of exp
    float p = expf(s - mx);
    float sm = p;
#pragma unroll
    for (int o = 16; o; o >>= 1) sm += __shfl_xor_sync(0xffffffffu, sm, o);
    if (lane == 0) red[wid] = sm;
    __syncthreads();
    if (t == 0) {
        float v = 0.f;
#pragma unroll
        for (int i = 0; i < 8; i++) v += red[i];
        bcast = v;
    }
    __syncthreads();
    const float inv = 1.0f / bcast;

    const float d = p * inv;
    out_dist[idx] = d;

    // entropy: -sum(d * log(clip(d, 1e-20, 1)))
    float et = d * logf(fminf(fmaxf(d, 1e-20f), 1.0f));
#pragma unroll
    for (int o = 16; o; o >>= 1) et += __shfl_xor_sync(0xffffffffu, et, o);
    __syncthreads();               // red reuse safety
    if (lane == 0) red[wid] = et;
    __syncthreads();
    if (t == 0) {
        float v = 0.f;
#pragma unroll
        for (int i = 0; i < 8; i++) v += red[i];
        out_entropy[b] = -v;
    }
}

// ---------------------------------------------------------------------------
extern "C" void kernel_launch(void* const* d_in, const int* in_sizes, int n_in,
                              void* d_out, int out_size)
{
    const int*   e        = (const int*)  d_in[0];
    const int*   q        = (const int*)  d_in[1];
    const int*   r_space  = (const int*)  d_in[2];
    const int*   e_space  = (const int*)  d_in[3];
    const int*   amask    = (const int*)  d_in[4];
    const float* H        = (const float*)d_in[5];
    const float* ent      = (const float*)d_in[6];
    const float* rel      = (const float*)d_in[7];
    const float* W1       = (const float*)d_in[8];
    const float* b1       = (const float*)d_in[9];
    const float* W2       = (const float*)d_in[10];
    const float* b2       = (const float*)d_in[11];

    float* out = (float*)d_out;
    float* out_dist    = out;                       // [Bn, An]
    float* out_entropy = out + (size_t)Bn * An;     // [Bn]

    float* scratch = nullptr;
    cudaGetSymbolAddress((void**)&scratch, g_scratch);
    float* X    = scratch + OFF_X;
    float* h1   = scratch + OFF_H1;
    float* X2   = scratch + OFF_X2;
    float* RS   = scratch + OFF_RS;
    float* relT = scratch + OFF_RELT;

    // 1. X = cat([E, H, Q])
    build_x_kernel<<<Bn, 256>>>(e, q, H, ent, rel, X);

    // 2. relT = relation_emb^T
    transpose_rel_kernel<<<(NR * RD + 255) / 256, 256>>>(rel, relT);

    // 3. h1 = relu(X @ W1 + b1)
    {
        dim3 grid((AD + 63) / 64, (Bn + 63) / 64);
        gemm64_kernel<<<grid, 256>>>(X, W1, b1, h1, Bn, AD, K1, K1, AD, AD, 0);
    }
    // 4. X2 = h1 @ W2 + b2
    {
        dim3 grid((AD + 63) / 64, (Bn + 63) / 64);
        gemm64_kernel<<<grid, 256>>>(h1, W2, b2, X2, Bn, AD, AD, AD, AD, AD, 1);
    }
    // 5. RS = X2[:, :200] @ relT  -> [Bn, NR]
    {
        dim3 grid((NR + 63) / 64, (Bn + 63) / 64);
        gemm64_kernel<<<grid, 256>>>(X2, relT, nullptr, RS, Bn, NR, RD, AD, NR, NR, 2);
    }
    // 6. entity-score gather + softmax + entropy
    score_softmax_kernel<<<Bn, 256>>>(r_space, e_space, amask, ent, X2, RS,
                                      out_dist, out_entropy);
}

// round 3
// speedup vs baseline: 1.0091x; 1.0091x over previous
#include <cuda_runtime.h>
#include <math.h>

// Problem constants
static constexpr int Bn  = 2048;   // batch
static constexpr int An  = 256;    // action space
static constexpr int NR  = 500;    // relations
static constexpr int ED  = 200;
static constexpr int RD  = 200;
static constexpr int HD  = 400;
static constexpr int AD  = 400;    // ED+RD
static constexpr int K1  = ED + HD + RD; // 800
static constexpr int RDP = 208;    // RD padded to multiple of 16 for GEMM 3

// Scratch layout (floats)
static constexpr size_t OFF_H1   = 0;                          // [Bn, 400]
static constexpr size_t OFF_X2   = OFF_H1 + (size_t)Bn*AD;     // [Bn, 400]
static constexpr size_t OFF_RS   = OFF_X2 + (size_t)Bn*AD;     // [Bn, 500]
static constexpr size_t OFF_RELT = OFF_RS + (size_t)Bn*NR;     // [208, 500]
static constexpr size_t SCRATCH_FLOATS = OFF_RELT + (size_t)RDP*NR;

__device__ float g_scratch[SCRATCH_FLOATS];

// ---------------------------------------------------------------------------
// Build relT [RDP, NR]: rows 0..199 = relation_emb^T, rows 200..207 = 0
// ---------------------------------------------------------------------------
__global__ void transpose_rel_kernel(const float* __restrict__ rel, float* __restrict__ relT)
{
    int t = blockIdx.x * blockDim.x + threadIdx.x;
    if (t < RDP * NR) {
        int k = t / NR, n = t % NR;
        relT[t] = (k < RD) ? rel[n * RD + k] : 0.0f;
    }
}

// ---------------------------------------------------------------------------
// 128x64 double-buffered fp32 GEMM.
// MODE_A: 0 = plain A[m*lda + k]; 1 = X composed on the fly:
//         k<200 -> ent[e[m]*200+k]; k<600 -> H[m*400+k-200]; else rel[q[m]*200+k-600]
// EPI: 0 = +bias, relu ; 1 = +bias ; 2 = plain
// 256 threads, 8x4 micro-tile, BK=16.
// Requires: M % 128 == 0, K % 16 == 0, N % 4 == 0, lda/ldb/ldc % 4 == 0,
//           A readable at columns 0..K-1 (pad B rows with zeros if K padded).
// ---------------------------------------------------------------------------
template<int MODE_A, int EPI>
__global__ __launch_bounds__(256)
void gemm128x64_kernel(const float* __restrict__ Ap,
                       const int* __restrict__ eIdx, const int* __restrict__ qIdx,
                       const float* __restrict__ H,
                       const float* __restrict__ ent, const float* __restrict__ rel,
                       const float* __restrict__ Bp, const float* __restrict__ bias,
                       float* __restrict__ Cp,
                       int M, int N, int K, int lda, int ldb, int ldc)
{
    __shared__ float As[2][16][132];  // [buf][k][m], padded
    __shared__ float Bs[2][16][68];   // [buf][k][n], padded

    const int t   = threadIdx.x;
    const int tx  = t & 15, ty = t >> 4;
    const int bm  = blockIdx.y * 128, bn = blockIdx.x * 64;

    const int aRow = t >> 1;           // 0..127 (one row per thread)
    const int aCol = (t & 1) * 8;      // 0 or 8
    const int bRow = t >> 4;           // 0..15
    const int bCol = (t & 15) * 4;     // 0..60

    const int m0 = bm + aRow;
    // Per-thread gather bases (fixed row)
    const float* arow = nullptr;
    const float* entRow = nullptr;
    const float* hRow = nullptr;
    const float* relRow = nullptr;
    if (MODE_A == 0) {
        arow = Ap + (size_t)m0 * lda;
    } else {
        entRow = ent + (size_t)eIdx[m0] * ED;
        hRow   = H   + (size_t)m0 * HD;
        relRow = rel + (size_t)qIdx[m0] * RD;
    }

    const int nB = bn + bCol;
    const bool bValid = (nB < N);

    float acc[8][4];
#pragma unroll
    for (int i = 0; i < 8; i++)
#pragma unroll
        for (int j = 0; j < 4; j++) acc[i][j] = 0.f;

    const int nTiles = K / 16;

    auto loadA4 = [&](int k) -> float4 {
        if (MODE_A == 0) {
            return *reinterpret_cast<const float4*>(arow + k);
        } else {
            if (k < ED)           return *reinterpret_cast<const float4*>(entRow + k);
            else if (k < ED + HD) return *reinterpret_cast<const float4*>(hRow + (k - ED));
            else                  return *reinterpret_cast<const float4*>(relRow + (k - ED - HD));
        }
    };

    // Prologue: tile 0
    float4 ra0 = loadA4(aCol);
    float4 ra1 = loadA4(aCol + 4);
    float4 rb = make_float4(0.f, 0.f, 0.f, 0.f);
    if (bValid) rb = *reinterpret_cast<const float4*>(Bp + (size_t)bRow * ldb + nB);

    int buf = 0;
    {
        As[0][aCol + 0][aRow] = ra0.x; As[0][aCol + 1][aRow] = ra0.y;
        As[0][aCol + 2][aRow] = ra0.z; As[0][aCol + 3][aRow] = ra0.w;
        As[0][aCol + 4][aRow] = ra1.x; As[0][aCol + 5][aRow] = ra1.y;
        As[0][aCol + 6][aRow] = ra1.z; As[0][aCol + 7][aRow] = ra1.w;
        *reinterpret_cast<float4*>(&Bs[0][bRow][bCol]) = rb;
    }
    __syncthreads();

    for (int tile = 0; tile < nTiles; tile++) {
        // Prefetch next tile into regs
        if (tile + 1 < nTiles) {
            int k0 = (tile + 1) * 16;
            ra0 = loadA4(k0 + aCol);
            ra1 = loadA4(k0 + aCol + 4);
            rb = make_float4(0.f, 0.f, 0.f, 0.f);
            if (bValid) rb = *reinterpret_cast<const float4*>(Bp + (size_t)(k0 + bRow) * ldb + nB);
        }

        // Compute from smem[buf]
#pragma unroll
        for (int kk = 0; kk < 16; kk++) {
            float4 a0 = *reinterpret_cast<const float4*>(&As[buf][kk][ty * 8]);
            float4 a1 = *reinterpret_cast<const float4*>(&As[buf][kk][ty * 8 + 4]);
            float4 b  = *reinterpret_cast<const float4*>(&Bs[buf][kk][tx * 4]);
            float ar[8] = {a0.x, a0.y, a0.z, a0.w, a1.x, a1.y, a1.z, a1.w};
            float br[4] = {b.x, b.y, b.z, b.w};
#pragma unroll
            for (int i = 0; i < 8; i++)
#pragma unroll
                for (int j = 0; j < 4; j++)
                    acc[i][j] += ar[i] * br[j];
        }

        // Store prefetched regs to the other buffer
        if (tile + 1 < nTiles) {
            int nb = buf ^ 1;
            As[nb][aCol + 0][aRow] = ra0.x; As[nb][aCol + 1][aRow] = ra0.y;
            As[nb][aCol + 2][aRow] = ra0.z; As[nb][aCol + 3][aRow] = ra0.w;
            As[nb][aCol + 4][aRow] = ra1.x; As[nb][aCol + 5][aRow] = ra1.y;
            As[nb][aCol + 6][aRow] = ra1.z; As[nb][aCol + 7][aRow] = ra1.w;
            *reinterpret_cast<float4*>(&Bs[nb][bRow][bCol]) = rb;
            __syncthreads();
            buf = nb;
        }
    }

    // Epilogue
    const int nOut = bn + tx * 4;
    if (nOut < N) {
        float4 bv = make_float4(0.f, 0.f, 0.f, 0.f);
        if (EPI < 2) bv = *reinterpret_cast<const float4*>(bias + nOut);
#pragma unroll
        for (int i = 0; i < 8; i++) {
            int m = bm + ty * 8 + i;
            float4 v;
            v.x = acc[i][0]; v.y = acc[i][1]; v.z = acc[i][2]; v.w = acc[i][3];
            if (EPI < 2) { v.x += bv.x; v.y += bv.y; v.z += bv.z; v.w += bv.w; }
            if (EPI == 0) {
                v.x = fmaxf(v.x, 0.f); v.y = fmaxf(v.y, 0.f);
                v.z = fmaxf(v.z, 0.f); v.w = fmaxf(v.w, 0.f);
            }
            *reinterpret_cast<float4*>(Cp + (size_t)m * ldc + nOut) = v;
        }
    }
}

// ---------------------------------------------------------------------------
// Scores + softmax + entropy. One block per batch row, 256 threads (one/action).
// score[b,a] = RS[b, r_space] + dot(ent_emb[e_space], X2[b,200:400]) - (1-mask)*1e9
// ---------------------------------------------------------------------------
__global__ __launch_bounds__(256)
void score_softmax_kernel(const int* __restrict__ r_space,
                          const int* __restrict__ e_space,
                          const int* __restrict__ mask,
                          const float* __restrict__ ent,
                          const float* __restrict__ X2,
                          const float* __restrict__ RS,
                          float* __restrict__ out_dist,
                          float* __restrict__ out_entropy)
{
    __shared__ float x2s[AD];
    __shared__ float red[8];
    __shared__ float bcast;

    const int b = blockIdx.x;
    const int t = threadIdx.x;
    const int lane = t & 31, wid = t >> 5;

    for (int i = t; i < AD; i += 256) x2s[i] = X2[(size_t)b * AD + i];
    __syncthreads();

    const int idx = b * An + t;
    const int r  = r_space[idx];
    const int ei = e_space[idx];
    const float m = (float)mask[idx];

    float s = RS[(size_t)b * NR + r];

    const float4* erow = reinterpret_cast<const float4*>(ent + (size_t)ei * ED);
    const float4* xv   = reinterpret_cast<const float4*>(x2s + RD);
    float acc = 0.f;
#pragma unroll
    for (int i = 0; i < ED / 4; i++) {
        float4 v = erow[i];
        float4 x = xv[i];
        acc += v.x * x.x;
        acc += v.y * x.y;
        acc += v.z * x.z;
        acc += v.w * x.w;
    }
    s += acc;
    s -= (1.0f - m) * 1e9f;

    // block max
    float mx = s;
#pragma unroll
    for (int o = 16; o; o >>= 1) mx = fmaxf(mx, __shfl_xor_sync(0xffffffffu, mx, o));
    if (lane == 0) red[wid] = mx;
    __syncthreads();
    if (t == 0) {
        float v = red[0];
#pragma unroll
        for (int i = 1; i < 8; i++) v = fmaxf(v, red[i]);
        bcast = v;
    }
    __syncthreads();
    mx = bcast;

    // block sum of exp
    float p = expf(s - mx);
    float sm = p;
#pragma unroll
    for (int o = 16; o; o >>= 1) sm += __shfl_xor_sync(0xffffffffu, sm, o);
    if (lane == 0) red[wid] = sm;
    __syncthreads();
    if (t == 0) {
        float v = 0.f;
#pragma unroll
        for (int i = 0; i < 8; i++) v += red[i];
        bcast = v;
    }
    __syncthreads();
    const float inv = 1.0f / bcast;

    const float d = p * inv;
    out_dist[idx] = d;

    // entropy: -sum(d * log(clip(d, 1e-20, 1)))
    float et = d * logf(fminf(fmaxf(d, 1e-20f), 1.0f));
#pragma unroll
    for (int o = 16; o; o >>= 1) et += __shfl_xor_sync(0xffffffffu, et, o);
    __syncthreads();
    if (lane == 0) red[wid] = et;
    __syncthreads();
    if (t == 0) {
        float v = 0.f;
#pragma unroll
        for (int i = 0; i < 8; i++) v += red[i];
        out_entropy[b] = -v;
    }
}

// ---------------------------------------------------------------------------
extern "C" void kernel_launch(void* const* d_in, const int* in_sizes, int n_in,
                              void* d_out, int out_size)
{
    const int*   e        = (const int*)  d_in[0];
    const int*   q        = (const int*)  d_in[1];
    const int*   r_space  = (const int*)  d_in[2];
    const int*   e_space  = (const int*)  d_in[3];
    const int*   amask    = (const int*)  d_in[4];
    const float* H        = (const float*)d_in[5];
    const float* ent      = (const float*)d_in[6];
    const float* rel      = (const float*)d_in[7];
    const float* W1       = (const float*)d_in[8];
    const float* b1       = (const float*)d_in[9];
    const float* W2       = (const float*)d_in[10];
    const float* b2       = (const float*)d_in[11];

    float* out = (float*)d_out;
    float* out_dist    = out;                       // [Bn, An]
    float* out_entropy = out + (size_t)Bn * An;     // [Bn]

    float* scratch = nullptr;
    cudaGetSymbolAddress((void**)&scratch, g_scratch);
    float* h1   = scratch + OFF_H1;
    float* X2   = scratch + OFF_X2;
    float* RS   = scratch + OFF_RS;
    float* relT = scratch + OFF_RELT;

    // 1. relT = relation_emb^T, zero-padded to 208 rows
    transpose_rel_kernel<<<(RDP * NR + 255) / 256, 256>>>(rel, relT);

    // 2. h1 = relu(X @ W1 + b1), X gathered on the fly from (ent[e], H, rel[q])
    {
        dim3 grid((AD + 63) / 64, Bn / 128);
        gemm128x64_kernel<1, 0><<<grid, 256>>>(nullptr, e, q, H, ent, rel,
                                               W1, b1, h1, Bn, AD, K1, 0, AD, AD);
    }
    // 3. X2 = h1 @ W2 + b2
    {
        dim3 grid((AD + 63) / 64, Bn / 128);
        gemm128x64_kernel<0, 1><<<grid, 256>>>(h1, nullptr, nullptr, nullptr, nullptr, nullptr,
                                               W2, b2, X2, Bn, AD, AD, AD, AD, AD);
    }
    // 4. RS = X2[:, :200] @ relT  -> [Bn, NR], K padded to 208 (relT rows 200..207 = 0)
    {
        dim3 grid((NR + 63) / 64, Bn / 128);
        gemm128x64_kernel<0, 2><<<grid, 256>>>(X2, nullptr, nullptr, nullptr, nullptr, nullptr,
                                               relT, nullptr, RS, Bn, NR, RDP, AD, NR, NR);
    }
    // 5. entity-score gather + softmax + entropy
    score_softmax_kernel<<<Bn, 256>>>(r_space, e_space, amask, ent, X2, RS,
                                      out_dist, out_entropy);
}

// round 4
// speedup vs baseline: 1.2019x; 1.1911x over previous
#include <cuda_runtime.h>
#include <math.h>

// Problem constants
static constexpr int Bn  = 2048;   // batch
static constexpr int An  = 256;    // action space
static constexpr int NR  = 500;    // relations
static constexpr int ED  = 200;
static constexpr int RD  = 200;
static constexpr int HD  = 400;
static constexpr int AD  = 400;    // ED+RD
static constexpr int K1  = ED + HD + RD; // 800
static constexpr int NC  = 704;    // combined C2 width: 200 (X2R) + 500 (RS) + 4 pad

// Scratch layout (floats)
static constexpr size_t OFF_H1 = 0;                          // [Bn, 400]
static constexpr size_t OFF_C2 = OFF_H1 + (size_t)Bn*AD;     // [Bn, 704]
static constexpr size_t OFF_BC = OFF_C2 + (size_t)Bn*NC;     // [400, 704]
static constexpr size_t OFF_BV = OFF_BC + (size_t)AD*NC;     // [704]
static constexpr size_t SCRATCH_FLOATS = OFF_BV + NC;

__device__ float g_scratch[SCRATCH_FLOATS];

// ---------------------------------------------------------------------------
// Prep: BC[:,0:200] = W2[:,200:400]; bc[0:200]=b2[200:400];
//       bc[200+n] = dot(b2[0:200], rel[n,:]); bc[700:704]=0
// grid = 84 blocks x 256
// ---------------------------------------------------------------------------
__global__ void prep_bc_kernel(const float* __restrict__ W2, const float* __restrict__ b2,
                               const float* __restrict__ rel,
                               float* __restrict__ BC, float* __restrict__ bc)
{
    const int blk = blockIdx.x, t = threadIdx.x;
    const int lane = t & 31, w = t >> 5;

    if (blk < 20) {
        // copy W2[:,200:400] -> BC[:,0:200] as float4 (20000 float4 total)
        for (int i = blk * 256 + t; i < AD * 50; i += 20 * 256) {
            int row = i / 50, col = i % 50;
            float4 v = *reinterpret_cast<const float4*>(W2 + (size_t)row * AD + 200 + col * 4);
            *reinterpret_cast<float4*>(BC + (size_t)row * NC + col * 4) = v;
        }
    } else if (blk == 20) {
        if (t < 200) bc[t] = b2[200 + t];
        if (t >= 200 && t < 204) bc[500 + t] = 0.0f;   // bc[700..703] = 0
    } else {
        // warps 0..503 over blocks 21..83: n = warp id; dot(b2[0:200], rel[n,:200])
        int n = (blk - 21) * 8 + w;
        if (n < NR) {
            const float4* r4 = reinterpret_cast<const float4*>(rel + (size_t)n * RD);
            const float4* b4 = reinterpret_cast<const float4*>(b2);
            float4 rv = r4[lane], bv = b4[lane];
            float p = rv.x * bv.x + rv.y * bv.y + rv.z * bv.z + rv.w * bv.w;
            if (lane < 18) {
                float4 rv2 = r4[32 + lane], bv2 = b4[32 + lane];
                p += rv2.x * bv2.x + rv2.y * bv2.y + rv2.z * bv2.z + rv2.w * bv2.w;
            }
#pragma unroll
            for (int o = 16; o; o >>= 1) p += __shfl_xor_sync(0xffffffffu, p, o);
            if (lane == 0) bc[200 + n] = p;
        }
    }
}

// ---------------------------------------------------------------------------
// 64x64 double-buffered fp32 GEMM, fully bounds-checked.
// MODE_A: 0 = A[m*lda+k] ; 1 = X composed: k<200 ent[e[m]], k<600 H[m], else rel[q[m]]
// MODE_B: 0 = B row-major [K,N] (ldb) ; 1 = B = rel-style [nb, K] row-major,
//             logical B[k][n] = Bsrc[n*ldb + k] (transposed on load)
// EPI: 0 = +bias, relu ; 1 = +bias ; 2 = plain
// 256 threads, 4x4 micro-tile, BK=16. Requires K%4==0, N%4==0, lda/ldb/ldc%4==0.
// ---------------------------------------------------------------------------
template<int MODE_A, int MODE_B, int EPI>
__global__ __launch_bounds__(256, 4)
void gemm64_kernel(const float* __restrict__ Ap,
                   const int* __restrict__ eIdx, const int* __restrict__ qIdx,
                   const float* __restrict__ H,
                   const float* __restrict__ ent, const float* __restrict__ rel,
                   const float* __restrict__ Bp, const float* __restrict__ bias,
                   float* __restrict__ Cp,
                   int M, int N, int K, int lda, int ldb, int ldc, int nb)
{
    __shared__ float As[2][16][68];
    __shared__ float Bs[2][16][68];

    const int t  = threadIdx.x;
    const int tx = t & 15, ty = t >> 4;
    const int bm = blockIdx.y * 64, bn = blockIdx.x * 64;

    // A load mapping: one float4/thread: row aRow (0..63), col aCol (0,4,8,12)
    const int aRow = t >> 2, aCol = (t & 3) * 4;
    const int m0 = bm + aRow;
    const bool aRowValid = (m0 < M);

    const float* arow = nullptr;
    const float* entRow = nullptr; const float* hRow = nullptr; const float* relRow = nullptr;
    if (MODE_A == 0) {
        if (aRowValid) arow = Ap + (size_t)m0 * lda;
    } else {
        entRow = ent + (size_t)eIdx[m0] * ED;
        hRow   = H   + (size_t)m0 * HD;
        relRow = rel + (size_t)qIdx[m0] * RD;
    }

    // B load mapping
    // MODE_B==0: row-major [K,N]: kb = t>>4 (0..15), nbc = (t&15)*4
    // MODE_B==1: from Bsrc[n][k]: nR = t>>2 (0..63), kC = (t&3)*4
    const int b0r = (MODE_B == 0) ? (t >> 4) : (t >> 2);
    const int b0c = (MODE_B == 0) ? ((t & 15) * 4) : ((t & 3) * 4);

    float acc[4][4];
#pragma unroll
    for (int i = 0; i < 4; i++)
#pragma unroll
        for (int j = 0; j < 4; j++) acc[i][j] = 0.f;

    const int nTiles = (K + 15) / 16;

    auto loadA = [&](int k0) -> float4 {
        float4 z = make_float4(0.f, 0.f, 0.f, 0.f);
        int k = k0 + aCol;
        if (!aRowValid || k >= K) return z;
        if (MODE_A == 0) {
            return *reinterpret_cast<const float4*>(arow + k);
        } else {
            if (k < ED)           return *reinterpret_cast<const float4*>(entRow + k);
            else if (k < ED + HD) return *reinterpret_cast<const float4*>(hRow + (k - ED));
            else                  return *reinterpret_cast<const float4*>(relRow + (k - ED - HD));
        }
    };
    auto loadB = [&](int k0) -> float4 {
        float4 z = make_float4(0.f, 0.f, 0.f, 0.f);
        if (MODE_B == 0) {
            int k = k0 + b0r, n = bn + b0c;
            if (k >= K || n >= N) return z;
            return *reinterpret_cast<const float4*>(Bp + (size_t)k * ldb + n);
        } else {
            int n = bn + b0r, k = k0 + b0c;
            if (n >= nb || k >= K) return z;
            return *reinterpret_cast<const float4*>(Bp + (size_t)n * ldb + k);
        }
    };
    auto stage = [&](int buf, float4 ra, float4 rb) {
        As[buf][aCol + 0][aRow] = ra.x; As[buf][aCol + 1][aRow] = ra.y;
        As[buf][aCol + 2][aRow] = ra.z; As[buf][aCol + 3][aRow] = ra.w;
        if (MODE_B == 0) {
            *reinterpret_cast<float4*>(&Bs[buf][b0r][b0c]) = rb;
        } else {
            Bs[buf][b0c + 0][b0r] = rb.x; Bs[buf][b0c + 1][b0r] = rb.y;
            Bs[buf][b0c + 2][b0r] = rb.z; Bs[buf][b0c + 3][b0r] = rb.w;
        }
    };

    float4 ra = loadA(0), rb = loadB(0);
    stage(0, ra, rb);
    __syncthreads();

    int buf = 0;
    for (int tile = 0; tile < nTiles; tile++) {
        if (tile + 1 < nTiles) {
            int k0 = (tile + 1) * 16;
            ra = loadA(k0);
            rb = loadB(k0);
        }
#pragma unroll
        for (int kk = 0; kk < 16; kk++) {
            float4 a = *reinterpret_cast<const float4*>(&As[buf][kk][ty * 4]);
            float4 b = *reinterpret_cast<const float4*>(&Bs[buf][kk][tx * 4]);
            float ar[4] = {a.x, a.y, a.z, a.w};
            float br[4] = {b.x, b.y, b.z, b.w};
#pragma unroll
            for (int i = 0; i < 4; i++)
#pragma unroll
                for (int j = 0; j < 4; j++)
                    acc[i][j] += ar[i] * br[j];
        }
        if (tile + 1 < nTiles) {
            int nbuf = buf ^ 1;
            stage(nbuf, ra, rb);
            __syncthreads();
            buf = nbuf;
        }
    }

    const int nOut = bn + tx * 4;
    if (nOut < N) {
        float4 bv = make_float4(0.f, 0.f, 0.f, 0.f);
        if (EPI < 2) bv = *reinterpret_cast<const float4*>(bias + nOut);
#pragma unroll
        for (int i = 0; i < 4; i++) {
            int m = bm + ty * 4 + i;
            if (m >= M) continue;
            float4 v;
            v.x = acc[i][0]; v.y = acc[i][1]; v.z = acc[i][2]; v.w = acc[i][3];
            if (EPI < 2) { v.x += bv.x; v.y += bv.y; v.z += bv.z; v.w += bv.w; }
            if (EPI == 0) {
                v.x = fmaxf(v.x, 0.f); v.y = fmaxf(v.y, 0.f);
                v.z = fmaxf(v.z, 0.f); v.w = fmaxf(v.w, 0.f);
            }
            *reinterpret_cast<float4*>(Cp + (size_t)m * ldc + nOut) = v;
        }
    }
}

// ---------------------------------------------------------------------------
// Scores + softmax + entropy, coalesced gather version.
// Block = one batch row, 256 threads (8 warps). Warp w handles actions w*32..w*32+31,
// one action at a time with a warp-cooperative coalesced row load + butterfly dot.
// score[b,a] = RS[b,r] + dot(ent[e_space], X2R[b]) - (1-mask)*1e9
//   X2R = C2[b, 0:200]  (== X2[b, 200:400]),  RS[b,r] = C2[b, 200+r]
// ---------------------------------------------------------------------------
__global__ __launch_bounds__(256)
void score_softmax_kernel(const int* __restrict__ r_space,
                          const int* __restrict__ e_space,
                          const int* __restrict__ mask,
                          const float* __restrict__ ent,
                          const float* __restrict__ C2,
                          float* __restrict__ out_dist,
                          float* __restrict__ out_entropy)
{
    __shared__ float x2r[ED];
    __shared__ float red[8];
    __shared__ float bcast;

    const int b = blockIdx.x;
    const int t = threadIdx.x;
    const int lane = t & 31, w = t >> 5;
    const float* c2row = C2 + (size_t)b * NC;

    for (int i = t; i < ED / 4; i += 256)
        reinterpret_cast<float4*>(x2r)[i] = reinterpret_cast<const float4*>(c2row)[i];
    __syncthreads();

    // per-lane X chunks (float4 idx lane, and 32+lane for lane<18; 50 float4 total)
    const float4 xa = reinterpret_cast<const float4*>(x2r)[lane];
    const float4 xb = (lane < 18) ? reinterpret_cast<const float4*>(x2r)[32 + lane]
                                  : make_float4(0.f, 0.f, 0.f, 0.f);

    const int idx = b * An + t;           // this thread's own action (a == t)
    const int myE = e_space[idx];
    const int myR = r_space[idx];
    const float myM = (float)mask[idx];
    const float myRS = c2row[200 + myR];

    float myScore = 0.f;
#pragma unroll 4
    for (int i = 0; i < 32; i++) {
        const int ei = __shfl_sync(0xffffffffu, myE, i);
        const float4* row = reinterpret_cast<const float4*>(ent + (size_t)ei * ED);
        float4 v = row[lane];
        float p = v.x * xa.x + v.y * xa.y + v.z * xa.z + v.w * xa.w;
        if (lane < 18) {
            float4 v2 = row[32 + lane];
            p += v2.x * xb.x + v2.y * xb.y + v2.z * xb.z + v2.w * xb.w;
        }
#pragma unroll
        for (int o = 16; o; o >>= 1) p += __shfl_xor_sync(0xffffffffu, p, o);
        if (lane == i) myScore = p;
    }
    myScore += myRS;
    myScore -= (1.0f - myM) * 1e9f;
    (void)w;

    // block max
    float mx = myScore;
#pragma unroll
    for (int o = 16; o; o >>= 1) mx = fmaxf(mx, __shfl_xor_sync(0xffffffffu, mx, o));
    if (lane == 0) red[w] = mx;
    __syncthreads();
    if (t == 0) {
        float v = red[0];
#pragma unroll
        for (int i = 1; i < 8; i++) v = fmaxf(v, red[i]);
        bcast = v;
    }
    __syncthreads();
    mx = bcast;

    // block sum of exp
    float p = expf(myScore - mx);
    float sm = p;
#pragma unroll
    for (int o = 16; o; o >>= 1) sm += __shfl_xor_sync(0xffffffffu, sm, o);
    if (lane == 0) red[w] = sm;
    __syncthreads();
    if (t == 0) {
        float v = 0.f;
#pragma unroll
        for (int i = 0; i < 8; i++) v += red[i];
        bcast = v;
    }
    __syncthreads();
    const float inv = 1.0f / bcast;

    const float d = p * inv;
    out_dist[idx] = d;

    // entropy
    float et = d * logf(fminf(fmaxf(d, 1e-20f), 1.0f));
#pragma unroll
    for (int o = 16; o; o >>= 1) et += __shfl_xor_sync(0xffffffffu, et, o);
    __syncthreads();
    if (lane == 0) red[w] = et;
    __syncthreads();
    if (t == 0) {
        float v = 0.f;
#pragma unroll
        for (int i = 0; i < 8; i++) v += red[i];
        out_entropy[b] = -v;
    }
}

// ---------------------------------------------------------------------------
extern "C" void kernel_launch(void* const* d_in, const int* in_sizes, int n_in,
                              void* d_out, int out_size)
{
    const int*   e        = (const int*)  d_in[0];
    const int*   q        = (const int*)  d_in[1];
    const int*   r_space  = (const int*)  d_in[2];
    const int*   e_space  = (const int*)  d_in[3];
    const int*   amask    = (const int*)  d_in[4];
    const float* H        = (const float*)d_in[5];
    const float* ent      = (const float*)d_in[6];
    const float* rel      = (const float*)d_in[7];
    const float* W1       = (const float*)d_in[8];
    const float* b1       = (const float*)d_in[9];
    const float* W2       = (const float*)d_in[10];
    const float* b2       = (const float*)d_in[11];

    float* out = (float*)d_out;
    float* out_dist    = out;                       // [Bn, An]
    float* out_entropy = out + (size_t)Bn * An;     // [Bn]

    float* scratch = nullptr;
    cudaGetSymbolAddress((void**)&scratch, g_scratch);
    float* h1 = scratch + OFF_H1;
    float* C2 = scratch + OFF_C2;
    float* BC = scratch + OFF_BC;
    float* bc = scratch + OFF_BV;

    // 1. BC[:,0:200] = W2[:,200:400]; bc vector
    prep_bc_kernel<<<84, 256>>>(W2, b2, rel, BC, bc);

    // 2. BC[:,200:704] = W2[:, :200] @ rel^T  (cols 700:704 come out 0)
    {
        dim3 grid((504 + 63) / 64, (AD + 63) / 64);   // (8, 7)
        gemm64_kernel<0, 1, 2><<<grid, 256>>>(W2, nullptr, nullptr, nullptr, nullptr, nullptr,
                                              rel, nullptr, BC + 200,
                                              AD, 504, RD, AD, RD, NC, NR);
    }
    // 3. h1 = relu(X @ W1 + b1), X gathered on the fly from (ent[e], H, rel[q])
    {
        dim3 grid((AD + 63) / 64, Bn / 64);           // (7, 32)
        gemm64_kernel<1, 0, 0><<<grid, 256>>>(nullptr, e, q, H, ent, rel,
                                              W1, b1, h1,
                                              Bn, AD, K1, 0, AD, AD, 0);
    }
    // 4. C2 = h1 @ BC + bc   -> [Bn, 704] = [X2R | RS | pad]
    {
        dim3 grid(NC / 64, Bn / 64);                  // (11, 32)
        gemm64_kernel<0, 0, 1><<<grid, 256>>>(h1, nullptr, nullptr, nullptr, nullptr, nullptr,
                                              BC, bc, C2,
                                              Bn, NC, AD, AD, NC, NC, 0);
    }
    // 5. coalesced entity-score gather + softmax + entropy
    score_softmax_kernel<<<Bn, 256>>>(r_space, e_space, amask, ent, C2,
                                      out_dist, out_entropy);
}